// round 2
// baseline (speedup 1.0000x reference)
#include <cuda_runtime.h>
#include <cuda_bf16.h>

// Problem constants (fixed shapes for this problem)
#define NN 50000
#define EE 800000
#define DD 128
#define HH 32

// -------- scratch (no allocations allowed) --------
__device__ __align__(16) float g_y1[NN * HH];    // x @ W1_l^T
__device__ __align__(16) float g_z1[NN * HH];    // x @ W1_r^T
__device__ float g_sl[NN];                       // h @ W2_l^T
__device__ float g_sr[NN];                       // h @ W2_r^T
__device__ int   g_cnt[NN];                      // per-dst edge count
__device__ int   g_rowptr[NN + 1];               // CSR row pointers
__device__ int   g_cur[NN];                      // reorder cursors
__device__ int   g_esrc[EE];                     // CSR-ordered src indices
__device__ int   g_is64;                         // edge_index dtype flag

__device__ __forceinline__ long long edge_at(const void* ei, long long pos, int is64) {
    if (is64) return ((const long long*)ei)[pos];
    return (long long)((const int*)ei)[pos];
}

// -------- init: detect dtype (block 0) + zero counts --------
__global__ void init_kernel(const unsigned* __restrict__ ei_words, int n) {
    if (blockIdx.x == 0) {
        __shared__ int flag;
        if (threadIdx.x == 0) flag = 1;
        __syncthreads();
        unsigned w = ei_words[2 * threadIdx.x + 1];  // high words if int64
        if (w != 0u) flag = 0;
        __syncthreads();
        if (threadIdx.x == 0) g_is64 = flag;
    }
    for (int i = blockIdx.x * blockDim.x + threadIdx.x; i < n;
         i += gridDim.x * blockDim.x)
        g_cnt[i] = 0;
}

// -------- histogram of dst --------
__global__ __launch_bounds__(256) void hist_kernel(const void* __restrict__ ei, long long E) {
    long long e = (long long)blockIdx.x * blockDim.x + threadIdx.x;
    if (e >= E) return;
    int is64 = g_is64;
    int dst = (int)edge_at(ei, E + e, is64);
    atomicAdd(&g_cnt[dst], 1);
}

// -------- single-block exclusive scan of counts -> rowptr, cur --------
__global__ __launch_bounds__(1024) void scan_kernel(int n) {
    const int CH = (NN + 1023) / 1024;  // 49
    int tid = threadIdx.x;
    int base = tid * CH;
    int lim = base + CH; if (lim > n) lim = n;
    int s = 0;
    for (int i = base; i < lim; i++) s += g_cnt[i];

    __shared__ int wsum[32];
    int lane = tid & 31, wid = tid >> 5;
    int v = s;
#pragma unroll
    for (int o = 1; o < 32; o <<= 1) {
        int t = __shfl_up_sync(0xFFFFFFFFu, v, o);
        if (lane >= o) v += t;
    }
    if (lane == 31) wsum[wid] = v;
    __syncthreads();
    if (wid == 0) {
        int w = wsum[lane];
#pragma unroll
        for (int o = 1; o < 32; o <<= 1) {
            int t = __shfl_up_sync(0xFFFFFFFFu, w, o);
            if (lane >= o) w += t;
        }
        wsum[lane] = w;
    }
    __syncthreads();
    int pref = v - s + (wid > 0 ? wsum[wid - 1] : 0);  // exclusive prefix for this thread
    for (int i = base; i < lim; i++) {
        g_rowptr[i] = pref;
        g_cur[i] = pref;
        pref += g_cnt[i];
    }
    if (base < n && lim == n) g_rowptr[n] = pref;  // total = E
}

// -------- reorder: build CSR-ordered src array --------
__global__ __launch_bounds__(256) void reorder_kernel(const void* __restrict__ ei, long long E) {
    long long e = (long long)blockIdx.x * blockDim.x + threadIdx.x;
    if (e >= E) return;
    int is64 = g_is64;
    int src = (int)edge_at(ei, e, is64);
    int dst = (int)edge_at(ei, E + e, is64);
    int pos = atomicAdd(&g_cur[dst], 1);
    g_esrc[pos] = src;
}

// -------- fused linear: y1 = x@W1_l^T, z1 = x@W1_r^T --------
// 32 nodes per block, 256 threads. smem: x tile + transposed combined W.
__global__ __launch_bounds__(256) void lin1_kernel(
    const float* __restrict__ x,
    const float* __restrict__ W1l,
    const float* __restrict__ W1r,
    int n)
{
    __shared__ float xs[32][DD];     // 16 KB
    __shared__ float wt[DD][64];     // 32 KB, wt[k][j] = W[j][k]
    int tid = threadIdx.x;
    int node0 = blockIdx.x * 32;

    for (int idx = tid; idx < DD * 64; idx += 256) {
        int k = idx >> 6, j = idx & 63;
        wt[k][j] = (j < HH) ? W1l[j * DD + k] : W1r[(j - HH) * DD + k];
    }
    int nvalid = n - node0; if (nvalid > 32) nvalid = 32;
    const float4* xg = (const float4*)(x + (size_t)node0 * DD);
    float4* xs4 = (float4*)&xs[0][0];
    for (int idx = tid; idx < 32 * (DD / 4); idx += 256) {
        int nn = idx / (DD / 4);
        xs4[idx] = (nn < nvalid) ? xg[idx] : make_float4(0.f, 0.f, 0.f, 0.f);
    }
    __syncthreads();

    int j  = tid & 63;    // output column (0..31 -> y1, 32..63 -> z1)
    int ng = tid >> 6;    // node group 0..3 (8 nodes each)
    float acc[8];
#pragma unroll
    for (int i = 0; i < 8; i++) acc[i] = 0.0f;

    for (int k = 0; k < DD; k += 4) {
        float w0 = wt[k][j], w1 = wt[k + 1][j], w2 = wt[k + 2][j], w3 = wt[k + 3][j];
#pragma unroll
        for (int i = 0; i < 8; i++) {
            float4 xv = *(const float4*)&xs[ng * 8 + i][k];
            acc[i] = fmaf(xv.x, w0, acc[i]);
            acc[i] = fmaf(xv.y, w1, acc[i]);
            acc[i] = fmaf(xv.z, w2, acc[i]);
            acc[i] = fmaf(xv.w, w3, acc[i]);
        }
    }

    float* outp = (j < HH) ? g_y1 : g_z1;
    int jj = j & 31;
#pragma unroll
    for (int i = 0; i < 8; i++) {
        int node = node0 + ng * 8 + i;
        if (node < n) outp[node * HH + jj] = acc[i];
    }
}

// -------- fused layer-1 gather + epilogue + layer-2 linear (warp/node) --------
__global__ __launch_bounds__(256) void aggepi_kernel(
    const float* __restrict__ b1,
    const float* __restrict__ W2l,
    const float* __restrict__ W2r,
    int n)
{
    int node = (blockIdx.x * blockDim.x + threadIdx.x) >> 5;
    int lane = threadIdx.x & 31;
    if (node >= n) return;
    int beg = g_rowptr[node], end = g_rowptr[node + 1];
    float acc = 0.0f;
    int j = beg;
    for (; j + 4 <= end; j += 4) {
        int s0 = g_esrc[j], s1 = g_esrc[j + 1], s2 = g_esrc[j + 2], s3 = g_esrc[j + 3];
        float v0 = g_y1[s0 * HH + lane];
        float v1 = g_y1[s1 * HH + lane];
        float v2 = g_y1[s2 * HH + lane];
        float v3 = g_y1[s3 * HH + lane];
        acc += (v0 + v1) + (v2 + v3);
    }
    for (; j < end; j++) acc += g_y1[g_esrc[j] * HH + lane];

    float deg = (float)(end - beg);
    float rdeg = 1.0f / fmaxf(deg, 1.0f);
    float hv = acc * rdeg + b1[lane] + g_z1[node * HH + lane];
    hv = fmaxf(hv, 0.0f);  // relu
    float sl = hv * W2l[lane];
    float sr = hv * W2r[lane];
#pragma unroll
    for (int o = 16; o; o >>= 1) {
        sl += __shfl_xor_sync(0xFFFFFFFFu, sl, o);
        sr += __shfl_xor_sync(0xFFFFFFFFu, sr, o);
    }
    if (lane == 0) { g_sl[node] = sl; g_sr[node] = sr; }
}

// -------- fused layer-2 gather + final sigmoid (thread/node) --------
__global__ __launch_bounds__(256) void agg2_kernel(const float* __restrict__ b2,
                                                   float* __restrict__ out, int n) {
    int i = blockIdx.x * blockDim.x + threadIdx.x;
    if (i >= n) return;
    int beg = g_rowptr[i], end = g_rowptr[i + 1];
    float a = 0.0f;
    int j = beg;
    for (; j + 4 <= end; j += 4) {
        int s0 = g_esrc[j], s1 = g_esrc[j + 1], s2 = g_esrc[j + 2], s3 = g_esrc[j + 3];
        a += (g_sl[s0] + g_sl[s1]) + (g_sl[s2] + g_sl[s3]);
    }
    for (; j < end; j++) a += g_sl[g_esrc[j]];
    float deg = (float)(end - beg);
    float v = a / fmaxf(deg, 1.0f) + b2[0] + g_sr[i];
    out[i] = 1.0f / (1.0f + expf(-v));
}

extern "C" void kernel_launch(void* const* d_in, const int* in_sizes, int n_in,
                              void* d_out, int out_size) {
    const float* x   = (const float*)d_in[0];
    const void*  ei  = d_in[1];
    const float* W1l = (const float*)d_in[2];
    const float* b1  = (const float*)d_in[3];
    const float* W1r = (const float*)d_in[4];
    const float* W2l = (const float*)d_in[5];
    const float* b2  = (const float*)d_in[6];
    const float* W2r = (const float*)d_in[7];
    float* out = (float*)d_out;

    int n = in_sizes[0] / DD;            // 50000
    long long E = in_sizes[1] / 2;       // 800000

    init_kernel<<<128, 256>>>((const unsigned*)ei, n);
    hist_kernel<<<(unsigned)((E + 255) / 256), 256>>>(ei, E);
    scan_kernel<<<1, 1024>>>(n);
    reorder_kernel<<<(unsigned)((E + 255) / 256), 256>>>(ei, E);
    lin1_kernel<<<(n + 31) / 32, 256>>>(x, W1l, W1r, n);
    aggepi_kernel<<<(n + 7) / 8, 256>>>(b1, W2l, W2r, n);
    agg2_kernel<<<(n + 255) / 256, 256>>>(b2, out, n);
}

// round 4
// speedup vs baseline: 2.5604x; 2.5604x over previous
#include <cuda_runtime.h>
#include <cuda_bf16.h>

// Problem constants (fixed shapes for this problem)
#define NN 50000
#define EE 800000
#define DD 128
#define HH 32

// -------- scratch (no allocations allowed) --------
__device__ __align__(16) float g_y1[NN * HH];    // x @ W1_l^T
__device__ __align__(16) float g_z1[NN * HH];    // x @ W1_r^T
__device__ __align__(16) float g_agg[NN * HH];   // scatter-sum of y1
__device__ float g_deg[NN];
__device__ float g_sl[NN];                       // h @ W2_l^T
__device__ float g_sr[NN];                       // h @ W2_r^T
__device__ float g_agg2[NN];                     // scatter-sum of s_l
__device__ int   g_is64;                         // edge_index dtype flag

__device__ __forceinline__ long long edge_at(const void* ei, long long pos, int is64) {
    if (is64) return ((const long long*)ei)[pos];
    return (long long)((const int*)ei)[pos];
}

// -------- init: detect dtype (block 0) + zero accumulators --------
__global__ void init_kernel(const unsigned* __restrict__ ei_words, int n) {
    if (blockIdx.x == 0) {
        __shared__ int flag;
        if (threadIdx.x == 0) flag = 1;
        __syncthreads();
        unsigned w = ei_words[2 * threadIdx.x + 1];  // high words if int64
        if (w != 0u) flag = 0;
        __syncthreads();
        if (threadIdx.x == 0) g_is64 = flag;
    }
    int total = n * HH + 2 * n;
    for (int i = blockIdx.x * blockDim.x + threadIdx.x; i < total;
         i += gridDim.x * blockDim.x) {
        if (i < n * HH)            g_agg[i] = 0.0f;
        else if (i < n * HH + n)   g_deg[i - n * HH] = 0.0f;
        else                       g_agg2[i - n * HH - n] = 0.0f;
    }
}

// -------- tf32 helpers --------
__device__ __forceinline__ unsigned f2tf32(float f) {
    unsigned u;
    asm("cvt.rna.tf32.f32 %0, %1;" : "=r"(u) : "f"(f));
    return u;
}
__device__ __forceinline__ void split_tf32(float f, unsigned& hi, unsigned& lo) {
    hi = f2tf32(f);
    float rem = f - __uint_as_float(hi);
    lo = f2tf32(rem);
}
__device__ __forceinline__ void mma_tf32(float* d, unsigned a0, unsigned a1,
                                         unsigned a2, unsigned a3,
                                         unsigned b0, unsigned b1) {
    asm volatile(
        "mma.sync.aligned.m16n8k8.row.col.f32.tf32.tf32.f32 "
        "{%0,%1,%2,%3}, {%4,%5,%6,%7}, {%8,%9}, {%0,%1,%2,%3};\n"
        : "+f"(d[0]), "+f"(d[1]), "+f"(d[2]), "+f"(d[3])
        : "r"(a0), "r"(a1), "r"(a2), "r"(a3), "r"(b0), "r"(b1));
}

// Dynamic smem layout: xs[64][132] then wt[128][72]
#define XS_STRIDE 132
#define WT_STRIDE 72
#define XS_ELEMS  (64 * XS_STRIDE)
#define WT_ELEMS  (128 * WT_STRIDE)
#define LIN1_SMEM_BYTES ((XS_ELEMS + WT_ELEMS) * (int)sizeof(float))

// -------- fused linear via 3xTF32 tensor cores --------
// Block: 128 threads / 4 warps; 64 nodes x 64 outputs per block, K=128.
// Each warp: 16 rows x 64 cols (8 n-frags), 16 k-chunks of 8.
__global__ __launch_bounds__(128) void lin1_mma_kernel(
    const float* __restrict__ x,
    const float* __restrict__ W1l,
    const float* __restrict__ W1r,
    int n)
{
    extern __shared__ float smem[];
    float (*xs)[XS_STRIDE] = (float (*)[XS_STRIDE])smem;            // 64 x 132
    float (*wt)[WT_STRIDE] = (float (*)[WT_STRIDE])(smem + XS_ELEMS); // 128 x 72

    int tid = threadIdx.x;
    int node0 = blockIdx.x * 64;

    // W transposed into smem: wt[k][j] = W[j][k] (coalesced gmem reads)
    for (int idx = tid; idx < DD * 64; idx += 128) {
        int k = idx & 127, j = idx >> 7;
        wt[k][j] = (j < HH) ? W1l[j * DD + k] : W1r[(j - HH) * DD + k];
    }
    // x tile (vectorized, zero-pad out-of-range rows)
    for (int idx = tid; idx < 64 * (DD / 4); idx += 128) {
        int r = idx >> 5, c4 = idx & 31;
        float4 v = (node0 + r < n)
                 ? ((const float4*)(x + (size_t)(node0 + r) * DD))[c4]
                 : make_float4(0.f, 0.f, 0.f, 0.f);
        *(float4*)&xs[r][c4 * 4] = v;
    }
    __syncthreads();

    int warp = tid >> 5, lane = tid & 31;
    int g = lane >> 2, tig = lane & 3;
    int m0 = warp * 16;

    float acc[8][4];
#pragma unroll
    for (int nt = 0; nt < 8; nt++)
#pragma unroll
        for (int c = 0; c < 4; c++) acc[nt][c] = 0.0f;

#pragma unroll
    for (int kc = 0; kc < 16; kc++) {
        int k0 = kc * 8;
        float a0 = xs[m0 + g][k0 + tig];
        float a1 = xs[m0 + g + 8][k0 + tig];
        float a2 = xs[m0 + g][k0 + tig + 4];
        float a3 = xs[m0 + g + 8][k0 + tig + 4];
        unsigned ah0, al0, ah1, al1, ah2, al2, ah3, al3;
        split_tf32(a0, ah0, al0); split_tf32(a1, ah1, al1);
        split_tf32(a2, ah2, al2); split_tf32(a3, ah3, al3);

#pragma unroll
        for (int nt = 0; nt < 8; nt++) {
            float b0f = wt[k0 + tig][nt * 8 + g];
            float b1f = wt[k0 + tig + 4][nt * 8 + g];
            unsigned bh0, bl0, bh1, bl1;
            split_tf32(b0f, bh0, bl0); split_tf32(b1f, bh1, bl1);
            mma_tf32(acc[nt], ah0, ah1, ah2, ah3, bh0, bh1);  // hi*hi
            mma_tf32(acc[nt], al0, al1, al2, al3, bh0, bh1);  // lo*hi
            mma_tf32(acc[nt], ah0, ah1, ah2, ah3, bl0, bl1);  // hi*lo
        }
    }

    // store: c0,c1 -> row m0+g, cols j,j+1 ; c2,c3 -> row m0+g+8
    int node_a = node0 + m0 + g;
    int node_b = node_a + 8;
#pragma unroll
    for (int nt = 0; nt < 8; nt++) {
        int j = nt * 8 + 2 * tig;
        float* base = (j < HH) ? g_y1 : g_z1;
        int jj = j & 31;
        if (node_a < n) *(float2*)&base[node_a * HH + jj] = make_float2(acc[nt][0], acc[nt][1]);
        if (node_b < n) *(float2*)&base[node_b * HH + jj] = make_float2(acc[nt][2], acc[nt][3]);
    }
}

// -------- layer-1 edge scatter: agg[dst] += y1[src], deg[dst] += 1 --------
// 8 threads per edge, float4 vector atomics (sm_90+).
__global__ __launch_bounds__(256) void scatter1_kernel(const void* __restrict__ ei, long long E) {
    long long t = (long long)blockIdx.x * blockDim.x + threadIdx.x;
    long long e = t >> 3;
    int sub = (int)(t & 7);
    if (e >= E) return;
    int is64 = g_is64;
    long long src = edge_at(ei, e, is64);
    long long dst = edge_at(ei, E + e, is64);
    float4 v = *(const float4*)&g_y1[src * HH + sub * 4];
    atomicAdd((float4*)&g_agg[dst * HH + sub * 4], v);
    if (sub == 0) atomicAdd(&g_deg[dst], 1.0f);
}

// -------- layer-1 epilogue + layer-2 linear (warp per node) --------
__global__ __launch_bounds__(256) void epi_kernel(
    const float* __restrict__ b1,
    const float* __restrict__ W2l,
    const float* __restrict__ W2r,
    int n)
{
    int warp = (blockIdx.x * blockDim.x + threadIdx.x) >> 5;
    int lane = threadIdx.x & 31;
    if (warp >= n) return;
    float deg = g_deg[warp];
    float rdeg = 1.0f / fmaxf(deg, 1.0f);
    float hv = g_agg[warp * HH + lane] * rdeg + b1[lane] + g_z1[warp * HH + lane];
    hv = fmaxf(hv, 0.0f);  // relu
    float sl = hv * W2l[lane];
    float sr = hv * W2r[lane];
#pragma unroll
    for (int o = 16; o; o >>= 1) {
        sl += __shfl_xor_sync(0xFFFFFFFFu, sl, o);
        sr += __shfl_xor_sync(0xFFFFFFFFu, sr, o);
    }
    if (lane == 0) { g_sl[warp] = sl; g_sr[warp] = sr; }
}

// -------- layer-2 edge scatter: agg2[dst] += s_l[src] --------
__global__ __launch_bounds__(256) void scatter2_kernel(const void* __restrict__ ei, long long E) {
    long long e = (long long)blockIdx.x * blockDim.x + threadIdx.x;
    if (e >= E) return;
    int is64 = g_is64;
    long long src = edge_at(ei, e, is64);
    long long dst = edge_at(ei, E + e, is64);
    atomicAdd(&g_agg2[dst], g_sl[src]);
}

// -------- final: sigmoid(agg2/deg + b2 + s_r) --------
__global__ __launch_bounds__(256) void final_kernel(const float* __restrict__ b2,
                                                    float* __restrict__ out, int n) {
    int i = blockIdx.x * blockDim.x + threadIdx.x;
    if (i >= n) return;
    float rdeg = 1.0f / fmaxf(g_deg[i], 1.0f);
    float v = g_agg2[i] * rdeg + b2[0] + g_sr[i];
    out[i] = 1.0f / (1.0f + expf(-v));
}

extern "C" void kernel_launch(void* const* d_in, const int* in_sizes, int n_in,
                              void* d_out, int out_size) {
    const float* x   = (const float*)d_in[0];
    const void*  ei  = d_in[1];
    const float* W1l = (const float*)d_in[2];
    const float* b1  = (const float*)d_in[3];
    const float* W1r = (const float*)d_in[4];
    const float* W2l = (const float*)d_in[5];
    const float* b2  = (const float*)d_in[6];
    const float* W2r = (const float*)d_in[7];
    float* out = (float*)d_out;

    int n = in_sizes[0] / DD;            // 50000
    long long E = in_sizes[1] / 2;       // 800000

    // opt-in to >48KB dynamic smem (context-level, graph-capture safe)
    cudaFuncSetAttribute(lin1_mma_kernel,
                         cudaFuncAttributeMaxDynamicSharedMemorySize,
                         LIN1_SMEM_BYTES);

    init_kernel<<<512, 256>>>((const unsigned*)ei, n);
    lin1_mma_kernel<<<(n + 63) / 64, 128, LIN1_SMEM_BYTES>>>(x, W1l, W1r, n);
    {
        long long threads = E * 8;
        scatter1_kernel<<<(unsigned)((threads + 255) / 256), 256>>>(ei, E);
    }
    epi_kernel<<<(n * 32 + 255) / 256, 256>>>(b1, W2l, W2r, n);
    scatter2_kernel<<<(unsigned)((E + 255) / 256), 256>>>(ei, E);
    final_kernel<<<(n + 255) / 256, 256>>>(b2, out, n);
}